// round 6
// baseline (speedup 1.0000x reference)
#include <cuda_runtime.h>

// AWBM bucket model, single-pass decoupled lookback, register-resident data path.
// Thread t owns 32 consecutive timesteps: reads its own 256B of input (16x float4),
// keeps diffs/excess/totals in one 32-register array, writes its own 128B output
// line (8x float4). No smem tile, no transposes. Warp-parallel CUB-style lookback
// for both the clamp-function (S) chain and the affine (B) chain.

#define NTH 256
#define EPT 32
#define CHUNK (NTH * EPT)       // 8192
#define MAX_CHUNKS 1024
#define POS_INF __int_as_float(0x7f800000)
#define NEG_INF __int_as_float(0xff800000)
#define FULL 0xffffffffu

__device__ uint4 g_st1[MAX_CHUNKS];   // {flag, a, l, h}
__device__ uint4 g_st2[MAX_CHUNKS];   // {flag, m, c, -}

struct Fn  { float a, l, h; };        // x -> min(max(x+a, l), h)
struct Aff { float m, c; };           // x -> m*x + c

__device__ __forceinline__ Fn fn_id() { Fn f; f.a = 0.f; f.l = NEG_INF; f.h = POS_INF; return f; }
__device__ __forceinline__ Fn fn_comb(Fn p, Fn n) {
    Fn r;
    r.a = p.a + n.a;
    r.l = fmaxf(p.l + n.a, n.l);
    r.h = fminf(fmaxf(p.h + n.a, n.l), n.h);
    return r;
}
__device__ __forceinline__ float fn_apply(Fn f, float x) {
    return fminf(fmaxf(x + f.a, f.l), f.h);
}
__device__ __forceinline__ Aff af_id() { Aff a; a.m = 1.f; a.c = 0.f; return a; }
__device__ __forceinline__ Aff af_comb(Aff p, Aff n) {
    Aff r; r.m = n.m * p.m; r.c = n.m * p.c + n.c; return r;
}

__device__ __forceinline__ uint4 ldv4(const uint4* p) {
    uint4 v;
    asm volatile("ld.volatile.global.v4.b32 {%0,%1,%2,%3}, [%4];"
                 : "=r"(v.x), "=r"(v.y), "=r"(v.z), "=r"(v.w) : "l"(p) : "memory");
    return v;
}
__device__ __forceinline__ void stv4(uint4* p, uint4 v) {
    asm volatile("st.volatile.global.v4.b32 [%0], {%1,%2,%3,%4};"
                 :: "l"(p), "r"(v.x), "r"(v.y), "r"(v.z), "r"(v.w) : "memory");
}

__global__ void k_reset() {
    int t = blockIdx.x * blockDim.x + threadIdx.x;
    if (t < MAX_CHUNKS) {
        uint4 z; z.x = 0; z.y = 0; z.z = 0; z.w = 0;
        stv4(&g_st1[t], z);
        stv4(&g_st2[t], z);
    }
}

// warp-parallel lookback, clamp-fn chain: returns exclusive prefix of tiles 0..c-1
__device__ Fn lookback1(int c, int lane) {
    Fn L = fn_id();
    int whi = c - 1;
    for (;;) {
        int wlo = whi - 31; if (wlo < 0) wlo = 0;
        int n = whi - wlo + 1;
        uint4 st; int flag;
        for (;;) {
            flag = 1;
            if (lane < n) { st = ldv4(&g_st1[wlo + lane]); flag = (int)st.x; }
            if (__all_sync(FULL, flag != 0)) break;
            __nanosleep(40);
        }
        Fn v = fn_id();
        if (lane < n) { v.a = __uint_as_float(st.y); v.l = __uint_as_float(st.z); v.h = __uint_as_float(st.w); }
        unsigned pm = __ballot_sync(FULL, (lane < n) && (flag == 2));
        int P = pm ? (31 - __clz(pm)) : -1;
        if (P >= 0 && lane < P) v = fn_id();
        Fn s = v;
#pragma unroll
        for (int off = 1; off < 32; off <<= 1) {
            Fn up;
            up.a = __shfl_up_sync(FULL, s.a, off);
            up.l = __shfl_up_sync(FULL, s.l, off);
            up.h = __shfl_up_sync(FULL, s.h, off);
            if (lane >= off) s = fn_comb(up, s);
        }
        Fn W;
        W.a = __shfl_sync(FULL, s.a, n - 1);
        W.l = __shfl_sync(FULL, s.l, n - 1);
        W.h = __shfl_sync(FULL, s.h, n - 1);
        Fn newL = fn_comb(W, L);
        if (P >= 0) return newL;
        L = newL;
        whi = wlo - 1;
    }
}

__device__ Aff lookback2(int c, int lane) {
    Aff L = af_id();
    int whi = c - 1;
    for (;;) {
        int wlo = whi - 31; if (wlo < 0) wlo = 0;
        int n = whi - wlo + 1;
        uint4 st; int flag;
        for (;;) {
            flag = 1;
            if (lane < n) { st = ldv4(&g_st2[wlo + lane]); flag = (int)st.x; }
            if (__all_sync(FULL, flag != 0)) break;
            __nanosleep(40);
        }
        Aff v = af_id();
        if (lane < n) { v.m = __uint_as_float(st.y); v.c = __uint_as_float(st.z); }
        unsigned pm = __ballot_sync(FULL, (lane < n) && (flag == 2));
        int P = pm ? (31 - __clz(pm)) : -1;
        if (P >= 0 && lane < P) v = af_id();
        Aff s = v;
#pragma unroll
        for (int off = 1; off < 32; off <<= 1) {
            Aff up;
            up.m = __shfl_up_sync(FULL, s.m, off);
            up.c = __shfl_up_sync(FULL, s.c, off);
            if (lane >= off) s = af_comb(up, s);
        }
        Aff W;
        W.m = __shfl_sync(FULL, s.m, n - 1);
        W.c = __shfl_sync(FULL, s.c, n - 1);
        Aff newL = af_comb(W, L);
        if (P >= 0) return newL;
        L = newL;
        whi = wlo - 1;
    }
}

__global__ void __launch_bounds__(NTH)
k_main(const float4* __restrict__ x4, const float2* __restrict__ x2,
       float* __restrict__ out, int T,
       const float* __restrict__ pbfi, const float* __restrict__ pk,
       const float* __restrict__ psmax) {
    __shared__ float swa[8], swl[8], swh[8];
    __shared__ float swm[8], swc[8];
    __shared__ float s_bc[2];    // S_in, B_in

    const float bfi = pbfi[0], k = pk[0], smax = psmax[0];
    const float ombfi = 1.f - bfi, omk = 1.f - k;
    const int c = blockIdx.x;
    const int base = c * CHUNK;
    const int nvalid = min(CHUNK, T - base);
    const int tid = threadIdx.x;
    const int lane = tid & 31;
    const int w = tid >> 5;
    const int j0 = tid * EPT;
    const bool full = (j0 + EPT <= nvalid);
    const int nmine = full ? EPT : max(0, nvalid - j0);

    float d[EPT];   // diffs -> excess -> totals, register resident

    // ---- load: thread-owned 256B segment (16x float4 = 32 timesteps) ----
    if (full) {
        const float4* xp = x4 + ((base + j0) >> 1);
#pragma unroll
        for (int i = 0; i < EPT / 2; i++) {
            float4 v = xp[i];
            d[2 * i]     = v.x - v.y;
            d[2 * i + 1] = v.z - v.w;
        }
    } else {
#pragma unroll
        for (int jj = 0; jj < EPT; jj++) {
            if (jj < nmine) {
                float2 v = x2[base + j0 + jj];
                d[jj] = v.x - v.y;
            } else d[jj] = 0.f;
        }
    }

    // ---- 1) per-thread clamp composition ----
    Fn f = fn_id();
#pragma unroll
    for (int jj = 0; jj < EPT; jj++) {
        if (jj < nmine) {
            float dd = d[jj];
            f.a += dd;
            f.l = fmaxf(f.l + dd, 0.f);
            f.h = fminf(fmaxf(f.h + dd, 0.f), smax);
        }
    }

    // ---- 2) warp inclusive scan ----
    Fn finc = f;
#pragma unroll
    for (int off = 1; off < 32; off <<= 1) {
        Fn up;
        up.a = __shfl_up_sync(FULL, finc.a, off);
        up.l = __shfl_up_sync(FULL, finc.l, off);
        up.h = __shfl_up_sync(FULL, finc.h, off);
        if (lane >= off) finc = fn_comb(up, finc);
    }
    if (lane == 31) { swa[w] = finc.a; swl[w] = finc.l; swh[w] = finc.h; }
    __syncthreads();

    // ---- 3) warp 0: combine warp aggregates, publish, lookback ----
    if (w == 0) {
        Fn wa = fn_id();
        if (lane < 8) { wa.a = swa[lane]; wa.l = swl[lane]; wa.h = swh[lane]; }
        Fn wsc = wa;
#pragma unroll
        for (int off = 1; off < 8; off <<= 1) {
            Fn up;
            up.a = __shfl_up_sync(FULL, wsc.a, off);
            up.l = __shfl_up_sync(FULL, wsc.l, off);
            up.h = __shfl_up_sync(FULL, wsc.h, off);
            if (lane >= off) wsc = fn_comb(up, wsc);
        }
        if (lane < 8) { swa[lane] = wsc.a; swl[lane] = wsc.l; swh[lane] = wsc.h; }
        Fn agg;
        agg.a = __shfl_sync(FULL, wsc.a, 7);
        agg.l = __shfl_sync(FULL, wsc.l, 7);
        agg.h = __shfl_sync(FULL, wsc.h, 7);
        if (lane == 0) {
            uint4 s;
            s.x = (c == 0) ? 2u : 1u;
            s.y = __float_as_uint(agg.a); s.z = __float_as_uint(agg.l); s.w = __float_as_uint(agg.h);
            stv4(&g_st1[c], s);
        }
        Fn pre = fn_id();
        if (c > 0) {
            pre = lookback1(c, lane);
            if (lane == 0) {
                Fn inc = fn_comb(pre, agg);
                uint4 s;
                s.x = 2u;
                s.y = __float_as_uint(inc.a); s.z = __float_as_uint(inc.l); s.w = __float_as_uint(inc.h);
                stv4(&g_st1[c], s);
            }
        }
        if (lane == 0) s_bc[0] = fn_apply(pre, 0.5f);   // S_init
    }
    __syncthreads();

    // ---- 4) per-thread start S; excess in-place + thread affine ----
    float S = s_bc[0];
    {
        Fn wex = fn_id();
        if (w > 0) { wex.a = swa[w - 1]; wex.l = swl[w - 1]; wex.h = swh[w - 1]; }
        Fn lex;
        lex.a = __shfl_up_sync(FULL, finc.a, 1);
        lex.l = __shfl_up_sync(FULL, finc.l, 1);
        lex.h = __shfl_up_sync(FULL, finc.h, 1);
        if (lane == 0) lex = fn_id();
        Fn tex = fn_comb(wex, lex);
        S = fn_apply(tex, S);
    }

    Aff af = af_id();
#pragma unroll
    for (int jj = 0; jj < EPT; jj++) {
        if (jj < nmine) {
            float dd = d[jj];
            S = fmaxf(S + dd, 0.f);
            float e = fmaxf(S - smax, 0.f);
            S -= e;
            d[jj] = e;
            af.c = af.c + bfi * e;
            float bf = omk * af.c; af.c = af.c - bf;
            float bm = omk * af.m; af.m = af.m - bm;
        }
    }

    // ---- 5) warp scan of affines ----
    Aff ainc = af;
#pragma unroll
    for (int off = 1; off < 32; off <<= 1) {
        Aff up;
        up.m = __shfl_up_sync(FULL, ainc.m, off);
        up.c = __shfl_up_sync(FULL, ainc.c, off);
        if (lane >= off) ainc = af_comb(up, ainc);
    }
    if (lane == 31) { swm[w] = ainc.m; swc[w] = ainc.c; }
    __syncthreads();

    // ---- 6) warp 0: combine, publish, lookback #2 ----
    if (w == 0) {
        Aff wa = af_id();
        if (lane < 8) { wa.m = swm[lane]; wa.c = swc[lane]; }
        Aff wsc = wa;
#pragma unroll
        for (int off = 1; off < 8; off <<= 1) {
            Aff up;
            up.m = __shfl_up_sync(FULL, wsc.m, off);
            up.c = __shfl_up_sync(FULL, wsc.c, off);
            if (lane >= off) wsc = af_comb(up, wsc);
        }
        if (lane < 8) { swm[lane] = wsc.m; swc[lane] = wsc.c; }
        Aff agg;
        agg.m = __shfl_sync(FULL, wsc.m, 7);
        agg.c = __shfl_sync(FULL, wsc.c, 7);
        if (lane == 0) {
            uint4 s;
            s.x = (c == 0) ? 2u : 1u;
            s.y = __float_as_uint(agg.m); s.z = __float_as_uint(agg.c); s.w = 0u;
            stv4(&g_st2[c], s);
        }
        Aff pre = af_id();
        if (c > 0) {
            pre = lookback2(c, lane);
            if (lane == 0) {
                Aff inc = af_comb(pre, agg);
                uint4 s;
                s.x = 2u;
                s.y = __float_as_uint(inc.m); s.z = __float_as_uint(inc.c); s.w = 0u;
                stv4(&g_st2[c], s);
            }
        }
        if (lane == 0) s_bc[1] = pre.m * 1.0f + pre.c;   // B_init = 1
    }
    __syncthreads();

    // ---- 7) per-thread start B; exact reference replay in-place ----
    float B = s_bc[1];
    {
        Aff wex = af_id();
        if (w > 0) { wex.m = swm[w - 1]; wex.c = swc[w - 1]; }
        Aff lex;
        lex.m = __shfl_up_sync(FULL, ainc.m, 1);
        lex.c = __shfl_up_sync(FULL, ainc.c, 1);
        if (lane == 0) lex = af_id();
        Aff tex = af_comb(wex, lex);
        B = tex.m * B + tex.c;
    }
#pragma unroll
    for (int jj = 0; jj < EPT; jj++) {
        if (jj < nmine) {
            float e = d[jj];
            float outflow = ombfi * e;
            B = B + bfi * e;
            float baseflow = omk * B;
            B = B - baseflow;
            d[jj] = outflow + baseflow;
        }
    }

    // ---- 8) store: thread-owned 128B output line (8x float4) ----
    if (full) {
        float4* op = (float4*)(out + base + j0);
#pragma unroll
        for (int i = 0; i < EPT / 4; i++) {
            float4 v;
            v.x = d[4 * i]; v.y = d[4 * i + 1]; v.z = d[4 * i + 2]; v.w = d[4 * i + 3];
            op[i] = v;
        }
    } else {
#pragma unroll
        for (int jj = 0; jj < EPT; jj++)
            if (jj < nmine) out[base + j0 + jj] = d[jj];
    }
}

extern "C" void kernel_launch(void* const* d_in, const int* in_sizes, int n_in,
                              void* d_out, int out_size) {
    const float4* x4   = (const float4*)d_in[0];
    const float2* x2   = (const float2*)d_in[0];
    const float*  BFI  = (const float*)d_in[1];
    const float*  K    = (const float*)d_in[2];
    const float*  Smax = (const float*)d_in[3];
    float* out = (float*)d_out;

    const int T  = in_sizes[0] / 2;
    const int NC = (T + CHUNK - 1) / CHUNK;   // 977 for T = 8e6

    k_reset<<<(MAX_CHUNKS + 255) / 256, 256>>>();
    k_main<<<NC, NTH>>>(x4, x2, out, T, BFI, K, Smax);
}